// round 3
// baseline (speedup 1.0000x reference)
#include <cuda_runtime.h>

#define VOCAB 32000
#define BATCH 4
#define SEQ   2048
#define NVEC  (VOCAB / 4)        // 8000 float4 per row
#define TOTAL (BATCH * SEQ)      // 8192 CTAs
#define NFIN  125                // finalizer CTAs: 125 * 256 threads * int4 = 128000 elems
#define N4    ((BATCH * VOCAB) / 4)   // 32000 int4

// Scratch histogram. Zero-initialized at module load; the fused finalize
// resets it after consuming, so it is zero at every kernel entry
// (correctness run and every graph replay).
__device__ int g_hist[BATCH * VOCAB];
__device__ unsigned g_done = 0;   // CTAs finished argmax+atomicAdd
__device__ unsigned g_fin  = 0;   // finalizer CTAs finished

// One CTA per (b, s) row: argmax over VOCAB -> atomicAdd into histogram.
// The last NFIN CTAs to finish (by ticket) then perform the finalize pass
// (clip/normalize/mask into out, and reset g_hist) — no second launch.
__global__ __launch_bounds__(256, 8)
void argmax_hist_fused_kernel(const float* __restrict__ logits,
                              float* __restrict__ out) {
    const int row = blockIdx.x;
    const float4* __restrict__ p =
        reinterpret_cast<const float4*>(logits + (size_t)row * VOCAB);

    float best = -3.402823466e+38f;
    int   bidx = 0;
    const int tid = threadIdx.x;

    // Strided float4 scan, streaming (evict-first) loads. Strict '>' keeps the
    // first (lowest-index) max within a thread, matching jnp.argmax.
    #pragma unroll 4
    for (int i = tid; i < NVEC; i += 256) {
        float4 v = __ldcs(p + i);
        int base = i << 2;
        if (v.x > best) { best = v.x; bidx = base;     }
        if (v.y > best) { best = v.y; bidx = base + 1; }
        if (v.z > best) { best = v.z; bidx = base + 2; }
        if (v.w > best) { best = v.w; bidx = base + 3; }
    }

    // Warp reduction (tie -> smaller index)
    #pragma unroll
    for (int off = 16; off > 0; off >>= 1) {
        float ov = __shfl_down_sync(0xFFFFFFFFu, best, off);
        int   oi = __shfl_down_sync(0xFFFFFFFFu, bidx, off);
        if (ov > best || (ov == best && oi < bidx)) { best = ov; bidx = oi; }
    }

    __shared__ float s_val[8];
    __shared__ int   s_idx[8];
    __shared__ int   s_ticket;
    const int wid = tid >> 5;
    const int lid = tid & 31;
    if (lid == 0) { s_val[wid] = best; s_idx[wid] = bidx; }
    __syncthreads();

    if (tid < 32) {
        best = (lid < 8) ? s_val[lid] : -3.402823466e+38f;
        bidx = (lid < 8) ? s_idx[lid] : 0x7FFFFFFF;
        #pragma unroll
        for (int off = 4; off > 0; off >>= 1) {
            float ov = __shfl_down_sync(0xFFFFFFFFu, best, off);
            int   oi = __shfl_down_sync(0xFFFFFFFFu, bidx, off);
            if (ov > best || (ov == best && oi < bidx)) { best = ov; bidx = oi; }
        }
        if (lid == 0) {
            const int b = row / SEQ;
            atomicAdd(&g_hist[b * VOCAB + bidx], 1);
            // Same thread: hist add -> fence -> ticket. Observing
            // g_done == TOTAL therefore implies all hist adds are visible.
            __threadfence();
            s_ticket = (int)atomicAdd(&g_done, 1u);
        }
    }
    __syncthreads();
    const int ticket = s_ticket;

    if (ticket < TOTAL - NFIN) return;   // not a finalizer CTA

    // ---- fused finalize: last NFIN CTAs by completion order ----
    if (tid == 0) {
        while (atomicAdd(&g_done, 0u) < (unsigned)TOTAL) __nanosleep(64);
    }
    __syncthreads();
    __threadfence();

    const int slice = ticket - (TOTAL - NFIN);     // 0 .. NFIN-1
    const int i = slice * 256 + tid;               // int4 index, < N4 always
    {
        int4* hp = reinterpret_cast<int4*>(g_hist) + i;
        int4 h = *hp;
        *hp = make_int4(0, 0, 0, 0);               // reset for next replay

        const int e0 = i << 2;
        const int v0 = e0 % VOCAB;                 // VOCAB % 4 == 0

        float4 o;
        o.x = (v0     <= 2) ? 0.0f : fminf((float)h.x, 4.0f) * 0.25f;
        o.y = (v0 + 1 <= 2) ? 0.0f : fminf((float)h.y, 4.0f) * 0.25f;
        o.z = (v0 + 2 <= 2) ? 0.0f : fminf((float)h.z, 4.0f) * 0.25f;
        o.w = (v0 + 3 <= 2) ? 0.0f : fminf((float)h.w, 4.0f) * 0.25f;
        reinterpret_cast<float4*>(out)[i] = o;
    }

    // Counter reset for the next replay: last finalizer clears both counters.
    if (tid == 0) {
        __threadfence();
        unsigned f = atomicAdd(&g_fin, 1u);
        if (f == NFIN - 1) {
            atomicExch(&g_done, 0u);
            atomicExch(&g_fin, 0u);
        }
    }
}

extern "C" void kernel_launch(void* const* d_in, const int* in_sizes, int n_in,
                              void* d_out, int out_size) {
    const float* logits = (const float*)d_in[0];
    float* out = (float*)d_out;
    argmax_hist_fused_kernel<<<TOTAL, 256>>>(logits, out);
}

// round 4
// speedup vs baseline: 1.0169x; 1.0169x over previous
#include <cuda_runtime.h>

#define VOCAB 32000
#define BATCH 4
#define SEQ   2048
#define NVEC  (VOCAB / 4)   // 8000 float4 per row
#define N4    ((BATCH * VOCAB) / 4)

// Scratch histogram. Zero-initialized at module load; finalize_kernel resets
// it to zero after consuming it, so it is zero at every argmax entry
// (correctness run and every graph replay).
__device__ int g_hist[BATCH * VOCAB];

// One CTA per (b, s) row: argmax over VOCAB, then atomicAdd into histogram.
__global__ __launch_bounds__(256, 8)
void argmax_hist_kernel(const float* __restrict__ logits) {
    const int row = blockIdx.x;                       // 0 .. B*S-1
    const float4* __restrict__ p =
        reinterpret_cast<const float4*>(logits + (size_t)row * VOCAB);

    float best = -3.402823466e+38f;
    int   bidx = 0;
    const int tid = threadIdx.x;

    // Strided float4 scan, streaming (evict-first) loads. Strict '>' keeps the
    // first (lowest-index) max within a thread, matching jnp.argmax.
    #pragma unroll 4
    for (int i = tid; i < NVEC; i += 256) {
        float4 v = __ldcs(p + i);
        int base = i << 2;
        if (v.x > best) { best = v.x; bidx = base;     }
        if (v.y > best) { best = v.y; bidx = base + 1; }
        if (v.z > best) { best = v.z; bidx = base + 2; }
        if (v.w > best) { best = v.w; bidx = base + 3; }
    }

    // Warp reduction (tie -> smaller index)
    #pragma unroll
    for (int off = 16; off > 0; off >>= 1) {
        float ov = __shfl_down_sync(0xFFFFFFFFu, best, off);
        int   oi = __shfl_down_sync(0xFFFFFFFFu, bidx, off);
        if (ov > best || (ov == best && oi < bidx)) { best = ov; bidx = oi; }
    }

    __shared__ float s_val[8];
    __shared__ int   s_idx[8];
    const int wid = tid >> 5;
    const int lid = tid & 31;
    if (lid == 0) { s_val[wid] = best; s_idx[wid] = bidx; }
    __syncthreads();

    if (wid == 0) {
        best = (lid < 8) ? s_val[lid] : -3.402823466e+38f;
        bidx = (lid < 8) ? s_idx[lid] : 0x7FFFFFFF;
        #pragma unroll
        for (int off = 4; off > 0; off >>= 1) {
            float ov = __shfl_down_sync(0xFFFFFFFFu, best, off);
            int   oi = __shfl_down_sync(0xFFFFFFFFu, bidx, off);
            if (ov > best || (ov == best && oi < bidx)) { best = ov; bidx = oi; }
        }
        if (lid == 0) {
            int b = row / SEQ;
            atomicAdd(&g_hist[b * VOCAB + bidx], 1);
        }
    }
    // Allow the dependent (PDL) finalize grid to begin launching while the
    // remaining CTAs of this grid drain. Safe: finalize's dependent loads sit
    // behind cudaGridDependencySynchronize(), which waits for THIS grid's
    // full completion (all hist atomics visible).
    cudaTriggerProgrammaticLaunchCompletion();
}

// out[b, v] = (v is special) ? 0 : min(hist, 4) / 4 ; also resets g_hist.
// Launched with programmatic stream serialization: prologue/ramp overlaps the
// argmax tail; cudaGridDependencySynchronize() gates the hist reads.
__global__ void finalize_kernel(float* __restrict__ out) {
    const int i = blockIdx.x * blockDim.x + threadIdx.x;   // int4 index

    cudaGridDependencySynchronize();

    if (i < N4) {
        int4* hp = reinterpret_cast<int4*>(g_hist) + i;
        int4 h = *hp;
        *hp = make_int4(0, 0, 0, 0);                       // reset for replay

        const int e0 = i << 2;
        const int v0 = e0 % VOCAB;                         // VOCAB % 4 == 0

        float4 o;
        o.x = (v0     <= 2) ? 0.0f : fminf((float)h.x, 4.0f) * 0.25f;
        o.y = (v0 + 1 <= 2) ? 0.0f : fminf((float)h.y, 4.0f) * 0.25f;
        o.z = (v0 + 2 <= 2) ? 0.0f : fminf((float)h.z, 4.0f) * 0.25f;
        o.w = (v0 + 3 <= 2) ? 0.0f : fminf((float)h.w, 4.0f) * 0.25f;
        reinterpret_cast<float4*>(out)[i] = o;
    }
}

extern "C" void kernel_launch(void* const* d_in, const int* in_sizes, int n_in,
                              void* d_out, int out_size) {
    const float* logits = (const float*)d_in[0];
    float* out = (float*)d_out;

    argmax_hist_kernel<<<BATCH * SEQ, 256>>>(logits);

    cudaLaunchConfig_t cfg = {};
    cfg.gridDim  = dim3((N4 + 255) / 256, 1, 1);
    cfg.blockDim = dim3(256, 1, 1);
    cudaLaunchAttribute attr[1];
    attr[0].id = cudaLaunchAttributeProgrammaticStreamSerialization;
    attr[0].val.programmaticStreamSerializationAllowed = 1;
    cfg.attrs = attr;
    cfg.numAttrs = 1;
    cudaLaunchKernelEx(&cfg, finalize_kernel, out);
}